// round 2
// baseline (speedup 1.0000x reference)
#include <cuda_runtime.h>

// GraphAggregation: out[b][d] = mean over 196 nodes of in[b][n*4 + d]
// in:  (B, 784) float32   out: (B, 4) float32
//
// HBM-streaming bound (~413 MB traffic). Persistent grid; each warp processes
// 2 rows per loop iteration: 12 full + 2 partial independent float4 loads are
// front-batched (high MLP), then two butterfly reductions, then lane 0 writes
// two adjacent float4s (32B contiguous store).

__global__ void __launch_bounds__(256, 8)
graph_agg_kernel(const float4* __restrict__ in, float4* __restrict__ out, int B)
{
    const int lane   = threadIdx.x & 31;
    const int warp   = (int)((blockIdx.x * (unsigned)blockDim.x + threadIdx.x) >> 5);
    const int nwarps = (int)((gridDim.x * (unsigned)blockDim.x) >> 5);

    for (int r = warp * 2; r < B; r += nwarps * 2) {
        const float4* rowA = in + (size_t)r * 196;
        const bool hasB = (r + 1) < B;
        const float4* rowB = rowA + 196;

        float ax = 0.f, ay = 0.f, az = 0.f, aw = 0.f;
        float bx = 0.f, by = 0.f, bz = 0.f, bw = 0.f;

        // Front-batched loads: 6 per row (196 = 6*32 + 4) — independent, high MLP.
        float4 va[6], vb[6];
        #pragma unroll
        for (int k = 0; k < 6; ++k) va[k] = __ldg(rowA + k * 32 + lane);
        if (hasB) {
            #pragma unroll
            for (int k = 0; k < 6; ++k) vb[k] = __ldg(rowB + k * 32 + lane);
        }
        float4 ta = make_float4(0.f, 0.f, 0.f, 0.f);
        float4 tb = make_float4(0.f, 0.f, 0.f, 0.f);
        if (lane < 4) {
            ta = __ldg(rowA + 192 + lane);
            if (hasB) tb = __ldg(rowB + 192 + lane);
        }

        #pragma unroll
        for (int k = 0; k < 6; ++k) {
            ax += va[k].x; ay += va[k].y; az += va[k].z; aw += va[k].w;
        }
        ax += ta.x; ay += ta.y; az += ta.z; aw += ta.w;
        if (hasB) {
            #pragma unroll
            for (int k = 0; k < 6; ++k) {
                bx += vb[k].x; by += vb[k].y; bz += vb[k].z; bw += vb[k].w;
            }
            bx += tb.x; by += tb.y; bz += tb.z; bw += tb.w;
        }

        // Butterfly reductions for both rows.
        #pragma unroll
        for (int off = 16; off > 0; off >>= 1) {
            ax += __shfl_xor_sync(0xffffffffu, ax, off);
            ay += __shfl_xor_sync(0xffffffffu, ay, off);
            az += __shfl_xor_sync(0xffffffffu, az, off);
            aw += __shfl_xor_sync(0xffffffffu, aw, off);
            bx += __shfl_xor_sync(0xffffffffu, bx, off);
            by += __shfl_xor_sync(0xffffffffu, by, off);
            bz += __shfl_xor_sync(0xffffffffu, bz, off);
            bw += __shfl_xor_sync(0xffffffffu, bw, off);
        }

        if (lane == 0) {
            const float s = 1.0f / 196.0f;
            out[r] = make_float4(ax * s, ay * s, az * s, aw * s);
            if (hasB)
                out[r + 1] = make_float4(bx * s, by * s, bz * s, bw * s);
        }
    }
}

extern "C" void kernel_launch(void* const* d_in, const int* in_sizes, int n_in,
                              void* d_out, int out_size)
{
    const float4* in  = (const float4*)d_in[0];
    float4*       out = (float4*)d_out;
    const int B = in_sizes[0] / 784;          // 131072

    const int threads = 256;                  // 8 warps/block
    const int blocks  = 152 * 8;              // persistent: 8 blocks per SM (152 SMs)

    graph_agg_kernel<<<blocks, threads>>>(in, out, B);
}

// round 5
// speedup vs baseline: 1.8581x; 1.8581x over previous
#include <cuda_runtime.h>

// GraphAggregation: out[b][d] = mean over 196 nodes of in[b][n*4 + d]
// in:  (B, 784) float32   out: (B, 4) float32
//
// HBM-streaming bound (~413 MB traffic, measured roofline ~6.5 TB/s).
// Each warp owns 2 ADJACENT rows (page/TLB locality, contiguous assignment).
// 13 independent float4 loads per warp iteration are front-batched for high
// MLP (12 full-warp loads + 1 merged tail load across lanes 0-7). No register
// cap tight enough to force serialization (launch_bounds min 3 CTAs -> ~85 regs).

__global__ void __launch_bounds__(256, 3)
graph_agg_kernel(const float4* __restrict__ in, float4* __restrict__ out, int B2)
{
    const int lane = threadIdx.x & 31;
    const int warp = (int)((blockIdx.x * (unsigned)blockDim.x + threadIdx.x) >> 5);
    if (warp >= B2) return;              // B2 = B/2 row-pairs

    const int r = warp * 2;
    const float4* rowA = in + (size_t)r * 196;
    const float4* rowB = rowA + 196;

    // ---- front-batched independent loads ----
    float4 va[6], vb[6];
    #pragma unroll
    for (int k = 0; k < 6; ++k) va[k] = __ldg(rowA + k * 32 + lane);
    #pragma unroll
    for (int k = 0; k < 6; ++k) vb[k] = __ldg(rowB + k * 32 + lane);

    // merged tail: lanes 0-3 load rowA[192..195], lanes 4-7 load rowB[192..195]
    float4 t = make_float4(0.f, 0.f, 0.f, 0.f);
    if (lane < 8) {
        const float4* tp = (lane < 4) ? (rowA + 192 + lane) : (rowB + 188 + lane);
        t = __ldg(tp);
    }

    // ---- accumulate ----
    float ax = 0.f, ay = 0.f, az = 0.f, aw = 0.f;
    float bx = 0.f, by = 0.f, bz = 0.f, bw = 0.f;
    #pragma unroll
    for (int k = 0; k < 6; ++k) {
        ax += va[k].x; ay += va[k].y; az += va[k].z; aw += va[k].w;
        bx += vb[k].x; by += vb[k].y; bz += vb[k].z; bw += vb[k].w;
    }
    if (lane < 4)              { ax += t.x; ay += t.y; az += t.z; aw += t.w; }
    else                       { bx += t.x; by += t.y; bz += t.z; bw += t.w; }

    // ---- butterfly reductions ----
    #pragma unroll
    for (int off = 16; off > 0; off >>= 1) {
        ax += __shfl_xor_sync(0xffffffffu, ax, off);
        ay += __shfl_xor_sync(0xffffffffu, ay, off);
        az += __shfl_xor_sync(0xffffffffu, az, off);
        aw += __shfl_xor_sync(0xffffffffu, aw, off);
        bx += __shfl_xor_sync(0xffffffffu, bx, off);
        by += __shfl_xor_sync(0xffffffffu, by, off);
        bz += __shfl_xor_sync(0xffffffffu, bz, off);
        bw += __shfl_xor_sync(0xffffffffu, bw, off);
    }

    if (lane == 0) {
        const float s = 1.0f / 196.0f;
        out[r]     = make_float4(ax * s, ay * s, az * s, aw * s);
        out[r + 1] = make_float4(bx * s, by * s, bz * s, bw * s);
    }
}

extern "C" void kernel_launch(void* const* d_in, const int* in_sizes, int n_in,
                              void* d_out, int out_size)
{
    const float4* in  = (const float4*)d_in[0];
    float4*       out = (float4*)d_out;
    const int B  = in_sizes[0] / 784;         // 131072 (even)
    const int B2 = B / 2;                     // row-pairs

    const int threads = 256;                  // 8 warps/block -> 16 rows/block
    const int blocks  = (B2 + 7) / 8;         // 8192

    graph_agg_kernel<<<blocks, threads>>>(in, out, B2);
}